// round 15
// baseline (speedup 1.0000x reference)
#include <cuda_runtime.h>
#include <cstdint>

// ---------------------------------------------------------------------------
// Problem constants (fixed by the reference)
// ---------------------------------------------------------------------------
constexpr int Bn  = 4;
constexpr int Hh  = 192;
constexpr int Ww  = 192;
constexpr int HW  = Hh * Ww;          // 36864
constexpr int PIX = Bn * HW;          // 147456
constexpr int CIN = 64;
constexpr int CB  = 16;
constexpr int CM  = 256;              // num_colors == CM here
constexpr int BPB = HW / 256;         // pixel chunks of 256 per batch = 144
constexpr int NCHUNK = Bn * BPB;      // 576 total chunks
constexpr int QGRID  = 576;           // 4 blocks/SM x 148 SMs = 592 slots >= 576

// Output layout: [transformed_img | m_sp | palette]
constexpr int OFF_T = 0;
constexpr int OFF_M = Bn * 3 * HW;
constexpr int OFF_P = OFF_M + Bn * CM * HW;

// ---------------------------------------------------------------------------
// Scratch (no allocations allowed -> device globals)
// ---------------------------------------------------------------------------
__device__ float    g_x[Bn * CB * HW];        // bottleneck pre-BN activations
__device__ unsigned g_keys[(size_t)PIX * 16]; // per-pixel packed (idx<<24 | sm_bits>>8)
__device__ float    g_bnsum[CB];
__device__ float    g_bnsq[CB];
__device__ float    g_scale[CB];
__device__ float    g_shift[CB];
__device__ float    g_num[Bn * 3 * CM];
__device__ float    g_den[Bn * CM];

// ---------------------------------------------------------------------------
// Kernel Z: zero the reduction scratch (graph replays reuse globals)
// ---------------------------------------------------------------------------
__global__ void kZero() {
    int t = threadIdx.x;
    for (int i = t; i < CB; i += 256)       { g_bnsum[i] = 0.f; g_bnsq[i] = 0.f; }
    for (int i = t; i < Bn * 3 * CM; i += 256) g_num[i] = 0.f;
    for (int i = t; i < Bn * CM; i += 256)     g_den[i] = 0.f;
}

// ---------------------------------------------------------------------------
// Kernel A: bottleneck 1x1 conv (64->16, exact fp32) + BN statistics
// (validated R6 version, unchanged)
// ---------------------------------------------------------------------------
__global__ __launch_bounds__(256) void kBneck(const float* __restrict__ bf,
                                              const float* __restrict__ wb,
                                              const float* __restrict__ bb) {
    __shared__ __align__(16) float wsh[CIN * CB];   // [c][o]
    __shared__ float sb[CB];
    __shared__ float ssum[CB], ssq[CB];

    int tid = threadIdx.x;
    for (int i = tid; i < CIN * CB; i += 256) {
        int o = i / CIN, c = i % CIN;
        wsh[c * CB + o] = wb[i];
    }
    if (tid < CB) { sb[tid] = bb[tid]; ssum[tid] = 0.f; ssq[tid] = 0.f; }
    __syncthreads();

    int b     = blockIdx.x / BPB;
    int chunk = blockIdx.x % BPB;
    int p     = chunk * 256 + tid;

    float acc[CB];
#pragma unroll
    for (int o = 0; o < CB; o++) acc[o] = sb[o];

    const float* bfp = bf + (size_t)b * CIN * HW + p;
    const float4* w4 = reinterpret_cast<const float4*>(wsh);
#pragma unroll 4
    for (int c = 0; c < CIN; c++) {
        float v = bfp[(size_t)c * HW];
#pragma unroll
        for (int q = 0; q < 4; q++) {
            float4 w = w4[c * 4 + q];
            acc[q * 4 + 0] = fmaf(v, w.x, acc[q * 4 + 0]);
            acc[q * 4 + 1] = fmaf(v, w.y, acc[q * 4 + 1]);
            acc[q * 4 + 2] = fmaf(v, w.z, acc[q * 4 + 2]);
            acc[q * 4 + 3] = fmaf(v, w.w, acc[q * 4 + 3]);
        }
    }

    float* xp = g_x + (size_t)b * CB * HW + p;
#pragma unroll
    for (int o = 0; o < CB; o++) xp[(size_t)o * HW] = acc[o];

    int lane = tid & 31;
#pragma unroll
    for (int o = 0; o < CB; o++) {
        float s = acc[o];
        float q = acc[o] * acc[o];
#pragma unroll
        for (int off = 16; off > 0; off >>= 1) {
            s += __shfl_xor_sync(0xffffffffu, s, off);
            q += __shfl_xor_sync(0xffffffffu, q, off);
        }
        if (lane == 0) {
            atomicAdd(&ssum[o], s);
            atomicAdd(&ssq[o], q);
        }
    }
    __syncthreads();
    if (tid < CB) {
        atomicAdd(&g_bnsum[tid], ssum[tid]);
        atomicAdd(&g_bnsq[tid], ssq[tid]);
    }
}

// ---------------------------------------------------------------------------
// Kernel B: fold BN into scale/shift
// ---------------------------------------------------------------------------
__global__ void kBNFold(const float* __restrict__ gamma,
                        const float* __restrict__ beta) {
    int t = threadIdx.x;
    if (t < CB) {
        const float n = (float)PIX;
        float mean = g_bnsum[t] / n;
        float var  = g_bnsq[t] / n - mean * mean;
        float sc   = gamma[t] * rsqrtf(var + 1e-5f);
        g_scale[t] = sc;
        g_shift[t] = beta[t] - mean * sc;
    }
}

// compare-exchange on parallel (val,id) arrays: ascending (min to lower index)
#define CEV(A, I, x, y)                                         \
    {                                                           \
        bool pr_ = A[x] > A[y];                                 \
        float tl_ = pr_ ? A[y] : A[x];                          \
        float th_ = pr_ ? A[x] : A[y];                          \
        int   il_ = pr_ ? I[y] : I[x];                          \
        int   ih_ = pr_ ? I[x] : I[y];                          \
        A[x] = tl_; A[y] = th_; I[x] = il_; I[y] = ih_;         \
    }

// ---------------------------------------------------------------------------
// Kernel C: fused BN+ReLU -> scalar mask GEMM (16->256) -> batched bitonic
//           top-16 -> softmax -> zero-fill + scatter m_sp -> palette accum
// __launch_bounds__(256,4): 64-reg target -> 4 blocks/SM = 32 warps (occupancy
// lever; R14 measured 3 blocks/24 warps as the binding constraint).
// ---------------------------------------------------------------------------
__global__ __launch_bounds__(256, 4) void kMask(const float* __restrict__ img,
                                                const float* __restrict__ wmask,
                                                float* __restrict__ out) {
    __shared__ __align__(16) float wm[CB * CM];   // transposed: wm[c*CM + k]
    __shared__ float snum[3 * CM];
    __shared__ float sden[CM];
    __shared__ float ssc[CB], ssh[CB];

    int tid = threadIdx.x;
    for (int i = tid; i < CB * CM; i += 256) {
        int k = i >> 4, c = i & 15;
        wm[c * CM + k] = wmask[i];
    }
    for (int i = tid; i < 3 * CM; i += 256) snum[i] = 0.f;
    for (int i = tid; i < CM; i += 256)     sden[i] = 0.f;
    if (tid < CB) { ssc[tid] = g_scale[tid]; ssh[tid] = g_shift[tid]; }
    __syncthreads();

    int b     = blockIdx.x / BPB;
    int chunk = blockIdx.x % BPB;
    int p     = chunk * 256 + tid;
    int gp    = b * HW + p;

    // m_sp zero-fill up front: stores drain underneath the ALU-heavy compute
    {
        float4* z4 = reinterpret_cast<float4*>(out + OFF_M + (size_t)b * CM * HW
                                               + (size_t)chunk * 256);
        const float4 zz = make_float4(0.f, 0.f, 0.f, 0.f);
#pragma unroll 8
        for (int j = tid; j < CM * 64; j += 256) {
            int k = j >> 6, q = j & 63;
            z4[(size_t)k * (HW / 4) + q] = zz;
        }
    }

    // BN + ReLU -> feat[16] (scalar: 16 regs, key to the 64-reg budget)
    float feat[CB];
    const float* xp = g_x + (size_t)b * CB * HW + p;
#pragma unroll
    for (int c = 0; c < CB; c++) {
        float xv = xp[(size_t)c * HW];
        feat[c] = fmaxf(fmaf(xv, ssc[c], ssh[c]), 0.f);
    }

    const float4* wmv = reinterpret_cast<const float4*>(wm);

    // -------- top-16 via batched bitonic merges (fixed cost, no divergence)
    // sv[] ascending (sv[0] = current 16th-best), si[] = color ids
    float sv[16];
    int   si[16];
#pragma unroll
    for (int i = 0; i < 16; i++) { sv[i] = -3.4e38f; si[i] = 0; }

#pragma unroll 1
    for (int k0 = 0; k0 < CM; k0 += 8) {
        float nv[8];
        int   ni[8];
#pragma unroll
        for (int j = 0; j < 8; j++) { nv[j] = 0.f; ni[j] = k0 + j; }
#pragma unroll
        for (int c = 0; c < CB; c++) {
            float f = feat[c];
            int base = (c * CM + k0) >> 2;
            float4 wA = wmv[base];
            float4 wB = wmv[base + 1];
            nv[0] = fmaf(f, wA.x, nv[0]);
            nv[1] = fmaf(f, wA.y, nv[1]);
            nv[2] = fmaf(f, wA.z, nv[2]);
            nv[3] = fmaf(f, wA.w, nv[3]);
            nv[4] = fmaf(f, wB.x, nv[4]);
            nv[5] = fmaf(f, wB.y, nv[5]);
            nv[6] = fmaf(f, wB.z, nv[6]);
            nv[7] = fmaf(f, wB.w, nv[7]);
        }

        // sort the 8 new candidates ascending: Batcher odd-even, 19 CEs
        CEV(nv, ni, 0, 1) CEV(nv, ni, 2, 3) CEV(nv, ni, 4, 5) CEV(nv, ni, 6, 7)
        CEV(nv, ni, 0, 2) CEV(nv, ni, 1, 3) CEV(nv, ni, 4, 6) CEV(nv, ni, 5, 7)
        CEV(nv, ni, 1, 2) CEV(nv, ni, 5, 6)
        CEV(nv, ni, 0, 4) CEV(nv, ni, 1, 5) CEV(nv, ni, 2, 6) CEV(nv, ni, 3, 7)
        CEV(nv, ni, 2, 4) CEV(nv, ni, 3, 5)
        CEV(nv, ni, 1, 2) CEV(nv, ni, 3, 4) CEV(nv, ni, 5, 6)

        // partial bitonic merge: keep top-16 of (sv ∪ nv); result is bitonic
#pragma unroll
        for (int i = 0; i < 8; i++) {
            bool pr = nv[7 - i] > sv[i];
            sv[i] = pr ? nv[7 - i] : sv[i];
            si[i] = pr ? ni[7 - i] : si[i];
        }

        // bitonic merge 16 -> ascending (stages 8,4,2,1)
#pragma unroll
        for (int i = 0; i < 8; i++)  CEV(sv, si, i, i + 8)
#pragma unroll
        for (int g = 0; g < 16; g += 8)
#pragma unroll
            for (int i = 0; i < 4; i++) CEV(sv, si, g + i, g + i + 4)
#pragma unroll
        for (int g = 0; g < 16; g += 4)
#pragma unroll
            for (int i = 0; i < 2; i++) CEV(sv, si, g + i, g + i + 2)
#pragma unroll
        for (int g = 0; g < 16; g += 2) CEV(sv, si, g, g + 1)
    }

    // -------- softmax over the 16 selected (TEMP = 1) ----------------------
    float vmax = sv[15];
    float sm[16];
    float s = 0.f;
#pragma unroll
    for (int i = 0; i < 16; i++) { sm[i] = __expf(sv[i] - vmax); s += sm[i]; }
    float inv = 1.0f / s;
#pragma unroll
    for (int i = 0; i < 16; i++) sm[i] *= inv;

    __syncthreads();   // zero-fill (cross-thread) must land before scatter

    float* mo = out + OFF_M + (size_t)b * CM * HW + p;
#pragma unroll
    for (int i = 0; i < 16; i++) mo[(size_t)si[i] * HW] = sm[i];

    // palette accumulation (full-precision sm) + compact key dump for recon
    float ir = img[((size_t)b * 3 + 0) * HW + p];
    float ig = img[((size_t)b * 3 + 1) * HW + p];
    float il = img[((size_t)b * 3 + 2) * HW + p];
#pragma unroll
    for (int i = 0; i < 16; i++) {
        atomicAdd(&sden[si[i]], sm[i]);
        atomicAdd(&snum[si[i]],          sm[i] * ir);
        atomicAdd(&snum[CM + si[i]],     sm[i] * ig);
        atomicAdd(&snum[2 * CM + si[i]], sm[i] * il);
        g_keys[(size_t)i * PIX + gp] =
            ((unsigned)si[i] << 24) | (__float_as_uint(sm[i]) >> 8);
    }

    __syncthreads();
    for (int i = tid; i < 3 * CM; i += 256) atomicAdd(&g_num[b * 3 * CM + i], snum[i]);
    for (int i = tid; i < CM; i += 256)     atomicAdd(&g_den[b * CM + i],     sden[i]);
}

// ---------------------------------------------------------------------------
// Kernel D: finalize palette
// ---------------------------------------------------------------------------
__global__ void kPalette(float* __restrict__ out) {
    int t = blockIdx.x * blockDim.x + threadIdx.x;
    if (t < Bn * CM) {
        int b = t / CM, k = t % CM;
        float inv = 1.f / (g_den[t] + 1e-8f);
#pragma unroll
        for (int c = 0; c < 3; c++) {
            out[OFF_P + b * 3 * CM + c * CM + k] = g_num[b * 3 * CM + c * CM + k] * inv;
        }
    }
}

// ---------------------------------------------------------------------------
// Kernel E: transformed_img from compact keys + palette
// ---------------------------------------------------------------------------
__global__ __launch_bounds__(256) void kRecon(float* __restrict__ out) {
    __shared__ float pal[3 * CM];
    int tid   = threadIdx.x;
    int b     = blockIdx.x / BPB;
    int chunk = blockIdx.x % BPB;
    for (int i = tid; i < 3 * CM; i += 256) pal[i] = out[OFF_P + b * 3 * CM + i];
    __syncthreads();

    int p  = chunk * 256 + tid;
    int gp = b * HW + p;
    float a0 = 0.f, a1 = 0.f, a2 = 0.f;
#pragma unroll
    for (int i = 0; i < 16; i++) {
        unsigned u = g_keys[(size_t)i * PIX + gp];
        int idx = u >> 24;
        float sm = __uint_as_float((u & 0x00FFFFFFu) << 8);
        a0 = fmaf(sm, pal[idx], a0);
        a1 = fmaf(sm, pal[CM + idx], a1);
        a2 = fmaf(sm, pal[2 * CM + idx], a2);
    }
    out[OFF_T + ((size_t)b * 3 + 0) * HW + p] = a0;
    out[OFF_T + ((size_t)b * 3 + 1) * HW + p] = a1;
    out[OFF_T + ((size_t)b * 3 + 2) * HW + p] = a2;
}

// ---------------------------------------------------------------------------
// Launch
// ---------------------------------------------------------------------------
extern "C" void kernel_launch(void* const* d_in, const int* in_sizes, int n_in,
                              void* d_out, int out_size) {
    const float* img   = (const float*)d_in[0];
    const float* bfeat = (const float*)d_in[1];
    const float* wb    = (const float*)d_in[2];
    const float* bb    = (const float*)d_in[3];
    const float* gam   = (const float*)d_in[4];
    const float* bet   = (const float*)d_in[5];
    const float* wmask = (const float*)d_in[6];
    float* out = (float*)d_out;

    kZero<<<1, 256>>>();
    kBneck<<<NCHUNK, 256>>>(bfeat, wb, bb);
    kBNFold<<<1, 32>>>(gam, bet);
    kMask<<<QGRID, 256>>>(img, wmask, out);
    kPalette<<<(Bn * CM + 255) / 256, 256>>>(out);
    kRecon<<<NCHUNK, 256>>>(out);
}

// round 16
// speedup vs baseline: 1.1158x; 1.1158x over previous
#include <cuda_runtime.h>
#include <cstdint>

// ---------------------------------------------------------------------------
// Problem constants (fixed by the reference)
// ---------------------------------------------------------------------------
constexpr int Bn  = 4;
constexpr int Hh  = 192;
constexpr int Ww  = 192;
constexpr int HW  = Hh * Ww;          // 36864
constexpr int PIX = Bn * HW;          // 147456
constexpr int CIN = 64;
constexpr int CB  = 16;
constexpr int CM  = 256;              // num_colors == CM here
constexpr int BPB = HW / 256;         // pixel chunks of 256 per batch = 144
constexpr int NCHUNK = Bn * BPB;      // 576 total chunks
constexpr int QGRID  = 444;           // 3 blocks/SM x 148 SMs = one full wave

// Output layout: [transformed_img | m_sp | palette]
constexpr int OFF_T = 0;
constexpr int OFF_M = Bn * 3 * HW;
constexpr int OFF_P = OFF_M + Bn * CM * HW;

// ---------------------------------------------------------------------------
// Scratch (no allocations allowed -> device globals)
// ---------------------------------------------------------------------------
__device__ float    g_x[Bn * CB * HW];        // bottleneck pre-BN activations
__device__ unsigned g_keys[(size_t)PIX * 16]; // per-pixel packed (idx<<24 | sm_bits>>8)
__device__ float    g_bnsum[CB];
__device__ float    g_bnsq[CB];
__device__ float    g_num[Bn * 3 * CM];
__device__ float    g_den[Bn * CM];
__device__ unsigned g_ctr;                    // work-queue counter for kMask

// ---------------------------------------------------------------------------
// f32x2 helpers (packed fp32: 2 IEEE fma.rn per instruction, per-half exact)
// ---------------------------------------------------------------------------
__device__ __forceinline__ unsigned long long ffma2(unsigned long long a,
                                                    unsigned long long b,
                                                    unsigned long long c) {
    unsigned long long r;
    asm("fma.rn.f32x2 %0, %1, %2, %3;" : "=l"(r) : "l"(a), "l"(b), "l"(c));
    return r;
}
__device__ __forceinline__ unsigned long long pack2(float lo, float hi) {
    unsigned long long r;
    asm("mov.b64 %0, {%1, %2};" : "=l"(r) : "f"(lo), "f"(hi));
    return r;
}
__device__ __forceinline__ void unpack2(unsigned long long p, float& lo, float& hi) {
    asm("mov.b64 {%0, %1}, %2;" : "=f"(lo), "=f"(hi) : "l"(p));
}

// ---------------------------------------------------------------------------
// Kernel Z: zero the reduction scratch (graph replays reuse globals)
// ---------------------------------------------------------------------------
__global__ void kZero() {
    int t = threadIdx.x;
    if (t == 0) g_ctr = 0u;
    for (int i = t; i < CB; i += 256)       { g_bnsum[i] = 0.f; g_bnsq[i] = 0.f; }
    for (int i = t; i < Bn * 3 * CM; i += 256) g_num[i] = 0.f;
    for (int i = t; i < Bn * CM; i += 256)     g_den[i] = 0.f;
}

// ---------------------------------------------------------------------------
// Kernel A: bottleneck 1x1 conv (64->16, exact fp32) + BN statistics
// (validated R6/R14 version, unchanged)
// ---------------------------------------------------------------------------
__global__ __launch_bounds__(256) void kBneck(const float* __restrict__ bf,
                                              const float* __restrict__ wb,
                                              const float* __restrict__ bb) {
    __shared__ __align__(16) float wsh[CIN * CB];   // [c][o]
    __shared__ float sb[CB];
    __shared__ float ssum[CB], ssq[CB];

    int tid = threadIdx.x;
    for (int i = tid; i < CIN * CB; i += 256) {
        int o = i / CIN, c = i % CIN;
        wsh[c * CB + o] = wb[i];
    }
    if (tid < CB) { sb[tid] = bb[tid]; ssum[tid] = 0.f; ssq[tid] = 0.f; }
    __syncthreads();

    int b     = blockIdx.x / BPB;
    int chunk = blockIdx.x % BPB;
    int p     = chunk * 256 + tid;

    float acc[CB];
#pragma unroll
    for (int o = 0; o < CB; o++) acc[o] = sb[o];

    const float* bfp = bf + (size_t)b * CIN * HW + p;
    const float4* w4 = reinterpret_cast<const float4*>(wsh);
#pragma unroll 4
    for (int c = 0; c < CIN; c++) {
        float v = bfp[(size_t)c * HW];
#pragma unroll
        for (int q = 0; q < 4; q++) {
            float4 w = w4[c * 4 + q];
            acc[q * 4 + 0] = fmaf(v, w.x, acc[q * 4 + 0]);
            acc[q * 4 + 1] = fmaf(v, w.y, acc[q * 4 + 1]);
            acc[q * 4 + 2] = fmaf(v, w.z, acc[q * 4 + 2]);
            acc[q * 4 + 3] = fmaf(v, w.w, acc[q * 4 + 3]);
        }
    }

    float* xp = g_x + (size_t)b * CB * HW + p;
#pragma unroll
    for (int o = 0; o < CB; o++) xp[(size_t)o * HW] = acc[o];

    int lane = tid & 31;
#pragma unroll
    for (int o = 0; o < CB; o++) {
        float s = acc[o];
        float q = acc[o] * acc[o];
#pragma unroll
        for (int off = 16; off > 0; off >>= 1) {
            s += __shfl_xor_sync(0xffffffffu, s, off);
            q += __shfl_xor_sync(0xffffffffu, q, off);
        }
        if (lane == 0) {
            atomicAdd(&ssum[o], s);
            atomicAdd(&ssq[o], q);
        }
    }
    __syncthreads();
    if (tid < CB) {
        atomicAdd(&g_bnsum[tid], ssum[tid]);
        atomicAdd(&g_bnsq[tid], ssq[tid]);
    }
}

// compare-exchange on parallel (val,id) arrays: ascending (min to lower index)
#define CEV(A, I, x, y)                                         \
    {                                                           \
        bool pr_ = A[x] > A[y];                                 \
        float tl_ = pr_ ? A[y] : A[x];                          \
        float th_ = pr_ ? A[x] : A[y];                          \
        int   il_ = pr_ ? I[y] : I[x];                          \
        int   ih_ = pr_ ? I[x] : I[y];                          \
        A[x] = tl_; A[y] = th_; I[x] = il_; I[y] = ih_;         \
    }

// ---------------------------------------------------------------------------
// Kernel C: persistent work-queue over 576 chunks (R14-validated), with the
// BN fold computed inline at block start (kBNFold eliminated). Per chunk:
//   fused BN+ReLU -> f32x2 mask GEMM (16->256) -> batched bitonic top-16
//   -> softmax -> zero-fill + scatter m_sp -> palette accumulation.
// ---------------------------------------------------------------------------
__global__ __launch_bounds__(256, 3) void kMask(const float* __restrict__ img,
                                                const float* __restrict__ wmask,
                                                const float* __restrict__ gamma,
                                                const float* __restrict__ beta,
                                                float* __restrict__ out) {
    __shared__ __align__(16) float wm[CB * CM];   // transposed: wm[c*CM + k]
    __shared__ float snum[3 * CM];
    __shared__ float sden[CM];
    __shared__ float ssc[CB], ssh[CB];
    __shared__ int   schunk;

    int tid = threadIdx.x;
    for (int i = tid; i < CB * CM; i += 256) {
        int k = i >> 4, c = i & 15;
        wm[c * CM + k] = wmask[i];
    }
    for (int i = tid; i < 3 * CM; i += 256) snum[i] = 0.f;
    for (int i = tid; i < CM; i += 256)     sden[i] = 0.f;
    if (tid < CB) {
        // BN fold inline (was kBNFold): redundant per block, trivially cheap
        const float n = (float)PIX;
        float mean = g_bnsum[tid] / n;
        float var  = g_bnsq[tid] / n - mean * mean;
        float sc   = gamma[tid] * rsqrtf(var + 1e-5f);
        ssc[tid] = sc;
        ssh[tid] = beta[tid] - mean * sc;
    }

    while (true) {
        if (tid == 0) schunk = (int)atomicAdd(&g_ctr, 1u);
        __syncthreads();             // broadcast chunk id; also orders prior
        int myc = schunk;            // iteration's snum/sden re-zero
        if (myc >= NCHUNK) break;

        int b     = myc / BPB;
        int chunk = myc % BPB;
        int p     = chunk * 256 + tid;
        int gp    = b * HW + p;

        // m_sp zero-fill up front: stores drain underneath the ALU compute
        {
            float4* z4 = reinterpret_cast<float4*>(out + OFF_M + (size_t)b * CM * HW
                                                   + (size_t)chunk * 256);
            const float4 zz = make_float4(0.f, 0.f, 0.f, 0.f);
#pragma unroll 8
            for (int j = tid; j < CM * 64; j += 256) {
                int k = j >> 6, q = j & 63;
                z4[(size_t)k * (HW / 4) + q] = zz;
            }
        }

        // BN + ReLU -> feat, pre-packed as (f,f) f32x2 pairs
        unsigned long long featp[CB];
        const float* xp = g_x + (size_t)b * CB * HW + p;
#pragma unroll
        for (int c = 0; c < CB; c++) {
            float xv = xp[(size_t)c * HW];
            float f  = fmaxf(fmaf(xv, ssc[c], ssh[c]), 0.f);
            featp[c] = pack2(f, f);
        }

        // f32x2 GEMM for one 8-output group (per-half chain == scalar fmaf)
#define GEMM8P(NV, K0)                                                          \
    { unsigned long long a0_ = 0ULL, a1_ = 0ULL, a2_ = 0ULL, a3_ = 0ULL;        \
      _Pragma("unroll") for (int c_ = 0; c_ < CB; c_++) {                       \
          const ulonglong2* wp_ =                                               \
              reinterpret_cast<const ulonglong2*>(wm + c_ * CM + (K0));         \
          ulonglong2 wA_ = wp_[0];                                              \
          ulonglong2 wB_ = wp_[1];                                              \
          a0_ = ffma2(featp[c_], wA_.x, a0_);                                   \
          a1_ = ffma2(featp[c_], wA_.y, a1_);                                   \
          a2_ = ffma2(featp[c_], wB_.x, a2_);                                   \
          a3_ = ffma2(featp[c_], wB_.y, a3_);                                   \
      }                                                                         \
      unpack2(a0_, NV[0], NV[1]); unpack2(a1_, NV[2], NV[3]);                   \
      unpack2(a2_, NV[4], NV[5]); unpack2(a3_, NV[6], NV[7]); }

        // ---- top-16 via batched bitonic merges (fixed cost, no divergence)
        float sv[16];
        int   si[16];
#pragma unroll
        for (int i = 0; i < 16; i++) { sv[i] = -3.4e38f; si[i] = 0; }

#pragma unroll 1
        for (int k0 = 0; k0 < CM; k0 += 8) {
            float nv[8];
            int   ni[8];
            GEMM8P(nv, k0)
#pragma unroll
            for (int j = 0; j < 8; j++) ni[j] = k0 + j;

            // sort the 8 new candidates ascending: Batcher odd-even, 19 CEs
            CEV(nv, ni, 0, 1) CEV(nv, ni, 2, 3) CEV(nv, ni, 4, 5) CEV(nv, ni, 6, 7)
            CEV(nv, ni, 0, 2) CEV(nv, ni, 1, 3) CEV(nv, ni, 4, 6) CEV(nv, ni, 5, 7)
            CEV(nv, ni, 1, 2) CEV(nv, ni, 5, 6)
            CEV(nv, ni, 0, 4) CEV(nv, ni, 1, 5) CEV(nv, ni, 2, 6) CEV(nv, ni, 3, 7)
            CEV(nv, ni, 2, 4) CEV(nv, ni, 3, 5)
            CEV(nv, ni, 1, 2) CEV(nv, ni, 3, 4) CEV(nv, ni, 5, 6)

            // partial bitonic merge: keep top-16 of (sv ∪ nv); result bitonic
#pragma unroll
            for (int i = 0; i < 8; i++) {
                bool pr = nv[7 - i] > sv[i];
                sv[i] = pr ? nv[7 - i] : sv[i];
                si[i] = pr ? ni[7 - i] : si[i];
            }

            // bitonic merge 16 -> ascending (stages 8,4,2,1)
#pragma unroll
            for (int i = 0; i < 8; i++)  CEV(sv, si, i, i + 8)
#pragma unroll
            for (int g = 0; g < 16; g += 8)
#pragma unroll
                for (int i = 0; i < 4; i++) CEV(sv, si, g + i, g + i + 4)
#pragma unroll
            for (int g = 0; g < 16; g += 4)
#pragma unroll
                for (int i = 0; i < 2; i++) CEV(sv, si, g + i, g + i + 2)
#pragma unroll
            for (int g = 0; g < 16; g += 2) CEV(sv, si, g, g + 1)
        }

        // ---- softmax over the 16 selected (TEMP = 1) ----------------------
        float vmax = sv[15];
        float sm[16];
        float s = 0.f;
#pragma unroll
        for (int i = 0; i < 16; i++) { sm[i] = __expf(sv[i] - vmax); s += sm[i]; }
        float inv = 1.0f / s;
#pragma unroll
        for (int i = 0; i < 16; i++) sm[i] *= inv;

        __syncthreads();   // zero-fill (cross-thread) must land before scatter

        float* mo = out + OFF_M + (size_t)b * CM * HW + p;
#pragma unroll
        for (int i = 0; i < 16; i++) mo[(size_t)si[i] * HW] = sm[i];

        // palette accumulation + compact key dump for recon
        float ir = img[((size_t)b * 3 + 0) * HW + p];
        float ig = img[((size_t)b * 3 + 1) * HW + p];
        float il = img[((size_t)b * 3 + 2) * HW + p];
#pragma unroll
        for (int i = 0; i < 16; i++) {
            atomicAdd(&sden[si[i]], sm[i]);
            atomicAdd(&snum[si[i]],          sm[i] * ir);
            atomicAdd(&snum[CM + si[i]],     sm[i] * ig);
            atomicAdd(&snum[2 * CM + si[i]], sm[i] * il);
            g_keys[(size_t)i * PIX + gp] =
                ((unsigned)si[i] << 24) | (__float_as_uint(sm[i]) >> 8);
        }

        __syncthreads();   // shared palette atomics done
        // flush per chunk (chunks on one block may belong to different b)
        for (int i = tid; i < 3 * CM; i += 256) {
            atomicAdd(&g_num[b * 3 * CM + i], snum[i]);
            snum[i] = 0.f;
        }
        for (int i = tid; i < CM; i += 256) {
            atomicAdd(&g_den[b * CM + i], sden[i]);
            sden[i] = 0.f;
        }
        // next loop-top __syncthreads orders the re-zero before reuse
    }
}

// ---------------------------------------------------------------------------
// Kernel E: palette finalize (inline, was kPalette) + transformed_img
// ---------------------------------------------------------------------------
__global__ __launch_bounds__(256) void kRecon(float* __restrict__ out) {
    __shared__ float pal[3 * CM];
    int tid   = threadIdx.x;
    int b     = blockIdx.x / BPB;
    int chunk = blockIdx.x % BPB;

    // compute palette in-block from g_num/g_den (complete after kMask)
    for (int i = tid; i < 3 * CM; i += 256) {
        int k = i & (CM - 1);
        pal[i] = g_num[b * 3 * CM + i] / (g_den[b * CM + k] + 1e-8f);
    }
    __syncthreads();

    // chunk-0 blocks write the palette output (4 blocks cover Bn*3*CM)
    if (chunk == 0) {
        for (int i = tid; i < 3 * CM; i += 256)
            out[OFF_P + b * 3 * CM + i] = pal[i];
    }

    int p  = chunk * 256 + tid;
    int gp = b * HW + p;
    float a0 = 0.f, a1 = 0.f, a2 = 0.f;
#pragma unroll
    for (int i = 0; i < 16; i++) {
        unsigned u = g_keys[(size_t)i * PIX + gp];
        int idx = u >> 24;
        float sm = __uint_as_float((u & 0x00FFFFFFu) << 8);
        a0 = fmaf(sm, pal[idx], a0);
        a1 = fmaf(sm, pal[CM + idx], a1);
        a2 = fmaf(sm, pal[2 * CM + idx], a2);
    }
    out[OFF_T + ((size_t)b * 3 + 0) * HW + p] = a0;
    out[OFF_T + ((size_t)b * 3 + 1) * HW + p] = a1;
    out[OFF_T + ((size_t)b * 3 + 2) * HW + p] = a2;
}

// ---------------------------------------------------------------------------
// Launch: 4 kernels (was 6)
// ---------------------------------------------------------------------------
extern "C" void kernel_launch(void* const* d_in, const int* in_sizes, int n_in,
                              void* d_out, int out_size) {
    const float* img   = (const float*)d_in[0];
    const float* bfeat = (const float*)d_in[1];
    const float* wb    = (const float*)d_in[2];
    const float* bb    = (const float*)d_in[3];
    const float* gam   = (const float*)d_in[4];
    const float* bet   = (const float*)d_in[5];
    const float* wmask = (const float*)d_in[6];
    float* out = (float*)d_out;

    kZero<<<1, 256>>>();
    kBneck<<<NCHUNK, 256>>>(bfeat, wb, bb);
    kMask<<<QGRID, 256>>>(img, wmask, gam, bet, out);
    kRecon<<<NCHUNK, 256>>>(out);
}